// round 5
// baseline (speedup 1.0000x reference)
#include <cuda_runtime.h>
#include <cuda_bf16.h>
#include <math.h>
#include <stdint.h>

// Problem constants
#define BATCH 4
#define LSEQ 4096
#define DDIM 256
#define NTOK (BATCH * LSEQ)   // 16384
#define INV_TAU 2.0f

// bf16 MMA tiling (projections): CTA 128x128, K staged 64, double buffered
#define GBM 128
#define GBN 128
#define GBK 64
#define GPAD 72
#define G_TILE_BYTES (GBM * GPAD * 2)      // 18432 per buffer
#define G_B_OFF (2 * G_TILE_BYTES)
#define G_SMEM_TOTAL (4 * G_TILE_BYTES)    // 73728

// fp8 Gram tiling: CTA 128x128, whole K=256 resident (single stage)
#define QROW 272                           // 256 bytes + 16 pad
#define Q_TILE_BYTES (128 * QROW)          // 34816
#define Q_SMEM_TOTAL (2 * Q_TILE_BYTES)    // 69632

// ---------------- scratch (device globals; no allocation allowed) -----------
__device__ __nv_bfloat16 g_X1h[NTOK * DDIM];
__device__ __nv_bfloat16 g_X2h[NTOK * DDIM];
__device__ __nv_bfloat16 g_W1h[DDIM * DDIM];
__device__ __nv_bfloat16 g_W2h[DDIM * DDIM];
__device__ __nv_bfloat16 g_Hh [NTOK * DDIM];
__device__ float g_Z1[NTOK * DDIM];
__device__ float g_Z2[NTOK * DDIM];
__device__ uint8_t g_Z1q[NTOK * DDIM];
__device__ uint8_t g_Z2q[NTOK * DDIM];
__device__ float g_R11 [NTOK];
__device__ float g_R22 [NTOK];
__device__ float g_R12r[NTOK];
__device__ float g_R12c[NTOK];
__device__ float g_D12 [NTOK];

// ---------------- PTX helpers ------------------------------------------------
__device__ __forceinline__ uint32_t smem_u32(const void* p) {
    uint32_t a;
    asm("{ .reg .u64 t; cvta.to.shared.u64 t, %1; cvt.u32.u64 %0, t; }"
        : "=r"(a) : "l"(p));
    return a;
}

__device__ __forceinline__ void cp_async16(uint32_t s, const void* g) {
    asm volatile("cp.async.cg.shared.global [%0], [%1], 16;" :: "r"(s), "l"(g));
}
__device__ __forceinline__ void cp_commit() {
    asm volatile("cp.async.commit_group;");
}
template <int N>
__device__ __forceinline__ void cp_wait() {
    asm volatile("cp.async.wait_group %0;" :: "n"(N));
}

__device__ __forceinline__ void ldm_x4(uint32_t& r0, uint32_t& r1, uint32_t& r2,
                                       uint32_t& r3, uint32_t addr) {
    asm volatile("ldmatrix.sync.aligned.m8n8.x4.shared.b16 {%0,%1,%2,%3}, [%4];"
                 : "=r"(r0), "=r"(r1), "=r"(r2), "=r"(r3) : "r"(addr));
}

__device__ __forceinline__ void mma_bf16(float* d, const uint32_t* a,
                                         const uint32_t* b) {
    asm volatile(
        "mma.sync.aligned.m16n8k16.row.col.f32.bf16.bf16.f32 "
        "{%0,%1,%2,%3}, {%4,%5,%6,%7}, {%8,%9}, {%0,%1,%2,%3};"
        : "+f"(d[0]), "+f"(d[1]), "+f"(d[2]), "+f"(d[3])
        : "r"(a[0]), "r"(a[1]), "r"(a[2]), "r"(a[3]), "r"(b[0]), "r"(b[1]));
}

__device__ __forceinline__ void mma_e4m3(float* d, const uint32_t* a,
                                         const uint32_t* b) {
    asm volatile(
        "mma.sync.aligned.m16n8k32.row.col.f32.e4m3.e4m3.f32 "
        "{%0,%1,%2,%3}, {%4,%5,%6,%7}, {%8,%9}, {%0,%1,%2,%3};"
        : "+f"(d[0]), "+f"(d[1]), "+f"(d[2]), "+f"(d[3])
        : "r"(a[0]), "r"(a[1]), "r"(a[2]), "r"(a[3]), "r"(b[0]), "r"(b[1]));
}

__device__ __forceinline__ uint16_t f2_e4m3x2(float lo, float hi) {
    uint16_t r;
    asm("cvt.rn.satfinite.e4m3x2.f32 %0, %1, %2;" : "=h"(r) : "f"(hi), "f"(lo));
    return r;
}

// ---------------- init / convert ---------------------------------------------
__global__ void zero_kernel() {
    int i = blockIdx.x * blockDim.x + threadIdx.x;
    if (i < NTOK) {
        g_R11[i] = 0.f; g_R22[i] = 0.f; g_R12r[i] = 0.f; g_R12c[i] = 0.f;
    }
}

__global__ void cvt_kernel(const float* __restrict__ src, int dstsel, int n4) {
    __nv_bfloat16* dst = (dstsel == 0) ? g_X1h : (dstsel == 1) ? g_X2h
                       : (dstsel == 2) ? g_W1h : g_W2h;
    int i = blockIdx.x * blockDim.x + threadIdx.x;
    if (i < n4) {
        float4 v = reinterpret_cast<const float4*>(src)[i];
        __nv_bfloat162* d = reinterpret_cast<__nv_bfloat162*>(dst) + i * 2;
        d[0] = __floats2bfloat162_rn(v.x, v.y);
        d[1] = __floats2bfloat162_rn(v.z, v.w);
    }
}

// ---------------- projection GEMM (bf16 MMA): C = act(A @ W^T + bias) --------
template <int ACT>
__global__ __launch_bounds__(256, 2)
void proj_mma(int srcsel, int wsel, const float* __restrict__ bias, int dstsel) {
    extern __shared__ __align__(128) char smem[];
    const uint32_t sbase = smem_u32(smem);

    const int tid  = threadIdx.x;
    const int wid  = tid >> 5;
    const int lane = tid & 31;

    const __nv_bfloat16* A = (srcsel == 0) ? g_X1h : (srcsel == 1) ? g_X2h : g_Hh;
    const __nv_bfloat16* W = (wsel == 1) ? g_W1h : g_W2h;
    float* Cf = (dstsel == 1) ? g_Z1 : g_Z2;

    const int bm = blockIdx.y * GBM;
    const int bn = blockIdx.x * GBN;
    const __nv_bfloat16* Abase = A + (size_t)bm * DDIM;
    const __nv_bfloat16* Bbase = W + (size_t)bn * DDIM;

    const int wm = (wid & 3) * 32;
    const int wn = (wid >> 2) * 64;

    float acc[2][8][4];
#pragma unroll
    for (int mi = 0; mi < 2; mi++)
#pragma unroll
        for (int nj = 0; nj < 8; nj++)
#pragma unroll
            for (int c = 0; c < 4; c++) acc[mi][nj][c] = 0.f;

    auto load_stage = [&](int buf, int kt) {
        const int kofs = kt * GBK;
#pragma unroll
        for (int it = 0; it < 4; it++) {
            int idx = tid + it * 256;
            int row = idx >> 3;
            int ch  = idx & 7;
            cp_async16(sbase + buf * G_TILE_BYTES + row * (GPAD * 2) + ch * 16,
                       Abase + (size_t)row * DDIM + kofs + ch * 8);
            cp_async16(sbase + G_B_OFF + buf * G_TILE_BYTES + row * (GPAD * 2) + ch * 16,
                       Bbase + (size_t)row * DDIM + kofs + ch * 8);
        }
    };

    load_stage(0, 0);
    cp_commit();

    int buf = 0;
#pragma unroll
    for (int kt = 0; kt < DDIM / GBK; kt++) {
        if (kt + 1 < DDIM / GBK) {
            load_stage(buf ^ 1, kt + 1);
            cp_commit();
            cp_wait<1>();
        } else {
            cp_wait<0>();
        }
        __syncthreads();

        const uint32_t aBuf = sbase + buf * G_TILE_BYTES;
        const uint32_t bBuf = sbase + G_B_OFF + buf * G_TILE_BYTES;

#pragma unroll
        for (int ks = 0; ks < GBK / 16; ks++) {
            uint32_t afr[2][4];
#pragma unroll
            for (int mi = 0; mi < 2; mi++) {
                int r = wm + mi * 16 + (lane & 15);
                int c = ks * 16 + (lane >> 4) * 8;
                ldm_x4(afr[mi][0], afr[mi][1], afr[mi][2], afr[mi][3],
                       aBuf + r * (GPAD * 2) + c * 2);
            }
            uint32_t bfr[4][4];
#pragma unroll
            for (int bi = 0; bi < 4; bi++) {
                int r = wn + bi * 16 + (lane & 7) + ((lane >> 4) << 3);
                int c = ks * 16 + ((lane >> 3) & 1) * 8;
                ldm_x4(bfr[bi][0], bfr[bi][1], bfr[bi][2], bfr[bi][3],
                       bBuf + r * (GPAD * 2) + c * 2);
            }
#pragma unroll
            for (int mi = 0; mi < 2; mi++)
#pragma unroll
                for (int bi = 0; bi < 4; bi++) {
                    mma_bf16(acc[mi][bi * 2 + 0], afr[mi], &bfr[bi][0]);
                    mma_bf16(acc[mi][bi * 2 + 1], afr[mi], &bfr[bi][2]);
                }
        }
        __syncthreads();
        buf ^= 1;
    }

#pragma unroll
    for (int mi = 0; mi < 2; mi++)
#pragma unroll
        for (int nj = 0; nj < 8; nj++) {
            int col = bn + wn + nj * 8 + (lane & 3) * 2;
            float b0 = __ldg(&bias[col]);
            float b1 = __ldg(&bias[col + 1]);
            int r0 = bm + wm + mi * 16 + (lane >> 2);
            float v00 = acc[mi][nj][0] + b0, v01 = acc[mi][nj][1] + b1;
            float v10 = acc[mi][nj][2] + b0, v11 = acc[mi][nj][3] + b1;
            if (ACT) {
                v00 = v00 > 0.f ? v00 : expm1f(v00);
                v01 = v01 > 0.f ? v01 : expm1f(v01);
                v10 = v10 > 0.f ? v10 : expm1f(v10);
                v11 = v11 > 0.f ? v11 : expm1f(v11);
                *reinterpret_cast<__nv_bfloat162*>(g_Hh + (size_t)r0 * DDIM + col)
                    = __floats2bfloat162_rn(v00, v01);
                *reinterpret_cast<__nv_bfloat162*>(g_Hh + (size_t)(r0 + 8) * DDIM + col)
                    = __floats2bfloat162_rn(v10, v11);
            } else {
                *reinterpret_cast<float2*>(Cf + (size_t)r0 * DDIM + col)
                    = make_float2(v00, v01);
                *reinterpret_cast<float2*>(Cf + (size_t)(r0 + 8) * DDIM + col)
                    = make_float2(v10, v11);
            }
        }
}

// ---------------- row normalization: f32 in place + e4m3 copy ----------------
__global__ void normalize_kernel() {
    float* Z = (blockIdx.y == 0) ? g_Z1 : g_Z2;
    uint8_t* Zq = (blockIdx.y == 0) ? g_Z1q : g_Z2q;
    int row  = blockIdx.x * 8 + (threadIdx.x >> 5);
    int lane = threadIdx.x & 31;
    float4* p = reinterpret_cast<float4*>(Z + (size_t)row * DDIM);
    float4 v0 = p[lane];
    float4 v1 = p[lane + 32];
    float s = v0.x*v0.x + v0.y*v0.y + v0.z*v0.z + v0.w*v0.w
            + v1.x*v1.x + v1.y*v1.y + v1.z*v1.z + v1.w*v1.w;
#pragma unroll
    for (int off = 16; off >= 1; off >>= 1) s += __shfl_xor_sync(0xffffffffu, s, off);
    float inv = 1.f / fmaxf(sqrtf(s), 1e-12f);
    v0.x *= inv; v0.y *= inv; v0.z *= inv; v0.w *= inv;
    v1.x *= inv; v1.y *= inv; v1.z *= inv; v1.w *= inv;
    p[lane] = v0; p[lane + 32] = v1;

    uint32_t q0 = (uint32_t)f2_e4m3x2(v0.x, v0.y)
                | ((uint32_t)f2_e4m3x2(v0.z, v0.w) << 16);
    uint32_t q1 = (uint32_t)f2_e4m3x2(v1.x, v1.y)
                | ((uint32_t)f2_e4m3x2(v1.z, v1.w) << 16);
    uint32_t* pq = reinterpret_cast<uint32_t*>(Zq + (size_t)row * DDIM);
    pq[lane] = q0;
    pq[lane + 32] = q1;
}

// ---------------- diagonal of exp(z1.z2/tau) (fp32) --------------------------
__global__ void diag_kernel() {
    int row  = blockIdx.x * 8 + (threadIdx.x >> 5);
    int lane = threadIdx.x & 31;
    const float4* p1 = reinterpret_cast<const float4*>(g_Z1 + (size_t)row * DDIM);
    const float4* p2 = reinterpret_cast<const float4*>(g_Z2 + (size_t)row * DDIM);
    float4 a0 = p1[lane], a1 = p1[lane + 32];
    float4 b0 = p2[lane], b1 = p2[lane + 32];
    float s = a0.x*b0.x + a0.y*b0.y + a0.z*b0.z + a0.w*b0.w
            + a1.x*b1.x + a1.y*b1.y + a1.z*b1.z + a1.w*b1.w;
#pragma unroll
    for (int off = 16; off >= 1; off >>= 1) s += __shfl_xor_sync(0xffffffffu, s, off);
    if (lane == 0) g_D12[row] = __expf(s * INV_TAU);
}

// ---------------- FP8 warp-MMA Gram ------------------------------------------
// SYM=1: A=B=Zq(sel); triangular tiles j>=i; rowsum->R, colsum->R (off-diag).
// SYM=0: A=Z1q, B=Z2q; full grid; rowsum->R12r, colsum->R12c.
template <int SYM>
__global__ __launch_bounds__(256, 2)
void gram_fp8(int sel) {
    const int iy = blockIdx.y, jx = blockIdx.x;
    if (SYM && jx < iy) return;
    const bool do_col = SYM ? (jx != iy) : true;

    extern __shared__ __align__(128) char smem[];
    const uint32_t sbase = smem_u32(smem);

    const int tid  = threadIdx.x;
    const int wid  = tid >> 5;
    const int lane = tid & 31;
    const int b    = blockIdx.z;

    const uint8_t* Aq;
    const uint8_t* Bq;
    float* rowsum;
    float* colsum;
    if (SYM) {
        const uint8_t* Zq = (sel == 1) ? g_Z1q : g_Z2q;
        Aq = Zq; Bq = Zq;
        rowsum = (sel == 1) ? g_R11 : g_R22;
        colsum = rowsum;
    } else {
        Aq = g_Z1q; Bq = g_Z2q;
        rowsum = g_R12r; colsum = g_R12c;
    }

    const int bm = iy * 128;
    const int bn = jx * 128;
    const uint8_t* Abase = Aq + ((size_t)b * LSEQ + bm) * DDIM;
    const uint8_t* Bbase = Bq + ((size_t)b * LSEQ + bn) * DDIM;

    const int wm = (wid & 3) * 32;
    const int wn = (wid >> 2) * 64;

    // ---- single-stage load: whole 128x256B A and B tiles
    const uint32_t sA = sbase;
    const uint32_t sB = sbase + Q_TILE_BYTES;
#pragma unroll
    for (int it = 0; it < 8; it++) {
        int idx = tid + it * 256;          // 0..2047
        int row = idx >> 4;                // 0..127
        int ch  = idx & 15;                // 16B chunk
        cp_async16(sA + row * QROW + ch * 16, Abase + (size_t)row * DDIM + ch * 16);
        cp_async16(sB + row * QROW + ch * 16, Bbase + (size_t)row * DDIM + ch * 16);
    }
    cp_commit();

    float acc[2][8][4];
#pragma unroll
    for (int mi = 0; mi < 2; mi++)
#pragma unroll
        for (int nj = 0; nj < 8; nj++)
#pragma unroll
            for (int c = 0; c < 4; c++) acc[mi][nj][c] = 0.f;

    cp_wait<0>();
    __syncthreads();

#pragma unroll
    for (int ks = 0; ks < DDIM / 32; ks++) {
        uint32_t afr[2][4];
#pragma unroll
        for (int mi = 0; mi < 2; mi++) {
            int r = wm + mi * 16 + (lane & 15);
            int c = ks * 32 + (lane >> 4) * 16;     // bytes
            ldm_x4(afr[mi][0], afr[mi][1], afr[mi][2], afr[mi][3],
                   sA + r * QROW + c);
        }
        uint32_t bfr[4][4];
#pragma unroll
        for (int bi = 0; bi < 4; bi++) {
            int r = wn + bi * 16 + (lane & 7) + ((lane >> 4) << 3);
            int c = ks * 32 + ((lane >> 3) & 1) * 16;  // bytes
            ldm_x4(bfr[bi][0], bfr[bi][1], bfr[bi][2], bfr[bi][3],
                   sB + r * QROW + c);
        }
#pragma unroll
        for (int mi = 0; mi < 2; mi++)
#pragma unroll
            for (int bi = 0; bi < 4; bi++) {
                mma_e4m3(acc[mi][bi * 2 + 0], afr[mi], &bfr[bi][0]);
                mma_e4m3(acc[mi][bi * 2 + 1], afr[mi], &bfr[bi][2]);
            }
    }

    // ---- epilogue: exp + row sums (+ col sums)
    float rs[2][2] = {{0.f, 0.f}, {0.f, 0.f}};
    float cs[8][2];
#pragma unroll
    for (int nj = 0; nj < 8; nj++) { cs[nj][0] = 0.f; cs[nj][1] = 0.f; }

#pragma unroll
    for (int mi = 0; mi < 2; mi++)
#pragma unroll
        for (int nj = 0; nj < 8; nj++) {
            float e0 = __expf(acc[mi][nj][0] * INV_TAU);
            float e1 = __expf(acc[mi][nj][1] * INV_TAU);
            float e2 = __expf(acc[mi][nj][2] * INV_TAU);
            float e3 = __expf(acc[mi][nj][3] * INV_TAU);
            rs[mi][0] += e0 + e1;
            rs[mi][1] += e2 + e3;
            cs[nj][0] += e0 + e2;
            cs[nj][1] += e1 + e3;
        }

#pragma unroll
    for (int off = 1; off <= 2; off <<= 1)
#pragma unroll
        for (int mi = 0; mi < 2; mi++) {
            rs[mi][0] += __shfl_xor_sync(0xffffffffu, rs[mi][0], off);
            rs[mi][1] += __shfl_xor_sync(0xffffffffu, rs[mi][1], off);
        }
    if ((lane & 3) == 0) {
#pragma unroll
        for (int mi = 0; mi < 2; mi++) {
            int row = bm + wm + mi * 16 + (lane >> 2);
            atomicAdd(&rowsum[(size_t)b * LSEQ + row], rs[mi][0]);
            atomicAdd(&rowsum[(size_t)b * LSEQ + row + 8], rs[mi][1]);
        }
    }

    if (do_col) {
#pragma unroll
        for (int off = 4; off <= 16; off <<= 1)
#pragma unroll
            for (int nj = 0; nj < 8; nj++) {
                cs[nj][0] += __shfl_xor_sync(0xffffffffu, cs[nj][0], off);
                cs[nj][1] += __shfl_xor_sync(0xffffffffu, cs[nj][1], off);
            }
        if (lane < 4) {
#pragma unroll
            for (int nj = 0; nj < 8; nj++) {
                int col = bn + wn + nj * 8 + lane * 2;
                atomicAdd(&colsum[(size_t)b * LSEQ + col], cs[nj][0]);
                atomicAdd(&colsum[(size_t)b * LSEQ + col + 1], cs[nj][1]);
            }
        }
    }
}

// ---------------- final scalar reduction -------------------------------------
__global__ void final_kernel(float* __restrict__ out) {
    __shared__ double sred[256];
    const float E2 = 7.3890560989306495f;   // exp(||z||^2 / tau) = exp(2)
    double acc = 0.0;
    for (int n = threadIdx.x; n < NTOK; n += 256) {
        float d1 = g_R11[n] + g_R12r[n] - E2;
        float d2 = g_R22[n] + g_R12c[n] - E2;
        acc += (double)(logf(d1) + logf(d2) - 2.f * logf(g_D12[n]));
    }
    sred[threadIdx.x] = acc;
    __syncthreads();
    for (int s = 128; s > 0; s >>= 1) {
        if (threadIdx.x < s) sred[threadIdx.x] += sred[threadIdx.x + s];
        __syncthreads();
    }
    if (threadIdx.x == 0) out[0] = (float)(sred[0] / (2.0 * BATCH));
}

// ---------------- launch -------------------------------------------------------
extern "C" void kernel_launch(void* const* d_in, const int* in_sizes, int n_in,
                              void* d_out, int out_size) {
    (void)in_sizes; (void)n_in; (void)out_size;
    const float* X1 = (const float*)d_in[0];
    const float* X2 = (const float*)d_in[1];
    const float* W1 = (const float*)d_in[2];
    const float* b1 = (const float*)d_in[3];
    const float* W2 = (const float*)d_in[4];
    const float* b2 = (const float*)d_in[5];
    float* out = (float*)d_out;

    cudaFuncSetAttribute(proj_mma<0>, cudaFuncAttributeMaxDynamicSharedMemorySize, G_SMEM_TOTAL);
    cudaFuncSetAttribute(proj_mma<1>, cudaFuncAttributeMaxDynamicSharedMemorySize, G_SMEM_TOTAL);
    cudaFuncSetAttribute(gram_fp8<0>, cudaFuncAttributeMaxDynamicSharedMemorySize, Q_SMEM_TOTAL);
    cudaFuncSetAttribute(gram_fp8<1>, cudaFuncAttributeMaxDynamicSharedMemorySize, Q_SMEM_TOTAL);

    zero_kernel<<<(NTOK + 255) / 256, 256>>>();

    const int NX4 = NTOK * DDIM / 4;
    const int NW4 = DDIM * DDIM / 4;
    cvt_kernel<<<NX4 / 256, 256>>>(X1, 0, NX4);
    cvt_kernel<<<NX4 / 256, 256>>>(X2, 1, NX4);
    cvt_kernel<<<NW4 / 256, 256>>>(W1, 2, NW4);
    cvt_kernel<<<NW4 / 256, 256>>>(W2, 3, NW4);

    dim3 gproj(DDIM / GBN, NTOK / GBM);
    proj_mma<1><<<gproj, 256, G_SMEM_TOTAL>>>(0, 1, b1, 0);   // H = ELU(X1 W1^T + b1)
    proj_mma<0><<<gproj, 256, G_SMEM_TOTAL>>>(2, 2, b2, 1);   // Z1 = H W2^T + b2
    proj_mma<1><<<gproj, 256, G_SMEM_TOTAL>>>(1, 1, b1, 0);   // H = ELU(X2 W1^T + b1)
    proj_mma<0><<<gproj, 256, G_SMEM_TOTAL>>>(2, 2, b2, 2);   // Z2 = H W2^T + b2

    normalize_kernel<<<dim3(NTOK / 8, 2), 256>>>();
    diag_kernel<<<NTOK / 8, 256>>>();

    dim3 ggram(LSEQ / 128, LSEQ / 128, BATCH);   // (32, 32, 4)
    gram_fp8<1><<<ggram, 256, Q_SMEM_TOTAL>>>(1);   // R11 (triangular)
    gram_fp8<1><<<ggram, 256, Q_SMEM_TOTAL>>>(2);   // R22 (triangular)
    gram_fp8<0><<<ggram, 256, Q_SMEM_TOTAL>>>(0);   // R12 row + col

    final_kernel<<<1, 256>>>(out);
}

// round 6
// speedup vs baseline: 1.1276x; 1.1276x over previous
#include <cuda_runtime.h>
#include <cuda_bf16.h>
#include <math.h>
#include <stdint.h>

// Problem constants
#define BATCH 4
#define LSEQ 4096
#define DDIM 256
#define NTOK (BATCH * LSEQ)   // 16384
#define L2SEQ (2 * LSEQ)      // 8192 concatenated rows per batch
#define INV_TAU 2.0f

// bf16 MMA tiling (projections)
#define GBM 128
#define GBN 128
#define GBK 64
#define GPAD 72
#define G_TILE_BYTES (GBM * GPAD * 2)      // 18432 per buffer
#define G_B_OFF (2 * G_TILE_BYTES)
#define G_SMEM_TOTAL (4 * G_TILE_BYTES)    // 73728

// fp8 Gram tiling: CTA 128x128, K=256 in two 128B stages, SW128 swizzle
#define QSTAGE_BYTES (128 * 128)           // 16384 per stage
#define Q_A_OFF 0
#define Q_B_OFF (2 * QSTAGE_BYTES)         // after A's 2 stages
#define Q_SMEM_TOTAL (4 * QSTAGE_BYTES)    // 65536
#define NTILE 64                           // 8192 / 128 tile rows per batch
#define NTRI (NTILE * (NTILE + 1) / 2)     // 2080 triangular tiles

// ---------------- scratch (device globals; no allocation allowed) -----------
__device__ __nv_bfloat16 g_X1h[NTOK * DDIM];
__device__ __nv_bfloat16 g_X2h[NTOK * DDIM];
__device__ __nv_bfloat16 g_W1h[DDIM * DDIM];
__device__ __nv_bfloat16 g_W2h[DDIM * DDIM];
__device__ __nv_bfloat16 g_H1h[NTOK * DDIM];
__device__ __nv_bfloat16 g_H2h[NTOK * DDIM];
__device__ float g_Z1[NTOK * DDIM];
__device__ float g_Z2[NTOK * DDIM];
__device__ uint8_t g_Zq[(size_t)BATCH * L2SEQ * DDIM];   // concat [Z1;Z2] fp8
__device__ float g_Rall[BATCH * L2SEQ];                  // rowsums of exp(G/tau)
__device__ float g_D12 [NTOK];

// ---------------- PTX helpers ------------------------------------------------
__device__ __forceinline__ uint32_t smem_u32(const void* p) {
    uint32_t a;
    asm("{ .reg .u64 t; cvta.to.shared.u64 t, %1; cvt.u32.u64 %0, t; }"
        : "=r"(a) : "l"(p));
    return a;
}

__device__ __forceinline__ void cp_async16(uint32_t s, const void* g) {
    asm volatile("cp.async.cg.shared.global [%0], [%1], 16;" :: "r"(s), "l"(g));
}
__device__ __forceinline__ void cp_commit() {
    asm volatile("cp.async.commit_group;");
}
template <int N>
__device__ __forceinline__ void cp_wait() {
    asm volatile("cp.async.wait_group %0;" :: "n"(N));
}

__device__ __forceinline__ void ldm_x4(uint32_t& r0, uint32_t& r1, uint32_t& r2,
                                       uint32_t& r3, uint32_t addr) {
    asm volatile("ldmatrix.sync.aligned.m8n8.x4.shared.b16 {%0,%1,%2,%3}, [%4];"
                 : "=r"(r0), "=r"(r1), "=r"(r2), "=r"(r3) : "r"(addr));
}

__device__ __forceinline__ void mma_bf16(float* d, const uint32_t* a,
                                         const uint32_t* b) {
    asm volatile(
        "mma.sync.aligned.m16n8k16.row.col.f32.bf16.bf16.f32 "
        "{%0,%1,%2,%3}, {%4,%5,%6,%7}, {%8,%9}, {%0,%1,%2,%3};"
        : "+f"(d[0]), "+f"(d[1]), "+f"(d[2]), "+f"(d[3])
        : "r"(a[0]), "r"(a[1]), "r"(a[2]), "r"(a[3]), "r"(b[0]), "r"(b[1]));
}

__device__ __forceinline__ void mma_e4m3(float* d, const uint32_t* a,
                                         const uint32_t* b) {
    asm volatile(
        "mma.sync.aligned.m16n8k32.row.col.f32.e4m3.e4m3.f32 "
        "{%0,%1,%2,%3}, {%4,%5,%6,%7}, {%8,%9}, {%0,%1,%2,%3};"
        : "+f"(d[0]), "+f"(d[1]), "+f"(d[2]), "+f"(d[3])
        : "r"(a[0]), "r"(a[1]), "r"(a[2]), "r"(a[3]), "r"(b[0]), "r"(b[1]));
}

__device__ __forceinline__ uint16_t f2_e4m3x2(float lo, float hi) {
    uint16_t r;
    asm("cvt.rn.satfinite.e4m3x2.f32 %0, %1, %2;" : "=h"(r) : "f"(hi), "f"(lo));
    return r;
}

// ---------------- converts -----------------------------------------------------
__global__ void cvtX_kernel(const float* __restrict__ X1,
                            const float* __restrict__ X2, int n4) {
    int i = blockIdx.x * blockDim.x + threadIdx.x;
    const float* src = (i < n4) ? X1 : X2;
    __nv_bfloat16* dst = (i < n4) ? g_X1h : g_X2h;
    int k = (i < n4) ? i : i - n4;
    if (i < 2 * n4) {
        float4 v = reinterpret_cast<const float4*>(src)[k];
        __nv_bfloat162* d = reinterpret_cast<__nv_bfloat162*>(dst) + k * 2;
        d[0] = __floats2bfloat162_rn(v.x, v.y);
        d[1] = __floats2bfloat162_rn(v.z, v.w);
    }
}

__global__ void cvtW_kernel(const float* __restrict__ W1,
                            const float* __restrict__ W2, int n4) {
    int i = blockIdx.x * blockDim.x + threadIdx.x;
    const float* src = (i < n4) ? W1 : W2;
    __nv_bfloat16* dst = (i < n4) ? g_W1h : g_W2h;
    int k = (i < n4) ? i : i - n4;
    if (i < 2 * n4) {
        float4 v = reinterpret_cast<const float4*>(src)[k];
        __nv_bfloat162* d = reinterpret_cast<__nv_bfloat162*>(dst) + k * 2;
        d[0] = __floats2bfloat162_rn(v.x, v.y);
        d[1] = __floats2bfloat162_rn(v.z, v.w);
    }
}

// ---------------- projection GEMM (bf16 MMA): C = act(A @ W^T + bias) --------
// ACT=1: A = X(z), W1, ELU -> H(z) bf16. ACT=0: A = H(z), W2 -> Z(z) f32.
template <int ACT>
__global__ __launch_bounds__(256, 2)
void proj_mma(const float* __restrict__ bias) {
    extern __shared__ __align__(128) char smem[];
    const uint32_t sbase = smem_u32(smem);

    const int tid  = threadIdx.x;
    const int wid  = tid >> 5;
    const int lane = tid & 31;
    const int z    = blockIdx.z;

    const __nv_bfloat16* A = ACT ? (z ? g_X2h : g_X1h) : (z ? g_H2h : g_H1h);
    const __nv_bfloat16* W = ACT ? g_W1h : g_W2h;
    __nv_bfloat16* Ch = z ? g_H2h : g_H1h;
    float* Cf = z ? g_Z2 : g_Z1;

    const int bm = blockIdx.y * GBM;
    const int bn = blockIdx.x * GBN;
    const __nv_bfloat16* Abase = A + (size_t)bm * DDIM;
    const __nv_bfloat16* Bbase = W + (size_t)bn * DDIM;

    const int wm = (wid & 3) * 32;
    const int wn = (wid >> 2) * 64;

    float acc[2][8][4];
#pragma unroll
    for (int mi = 0; mi < 2; mi++)
#pragma unroll
        for (int nj = 0; nj < 8; nj++)
#pragma unroll
            for (int c = 0; c < 4; c++) acc[mi][nj][c] = 0.f;

    auto load_stage = [&](int buf, int kt) {
        const int kofs = kt * GBK;
#pragma unroll
        for (int it = 0; it < 4; it++) {
            int idx = tid + it * 256;
            int row = idx >> 3;
            int ch  = idx & 7;
            cp_async16(sbase + buf * G_TILE_BYTES + row * (GPAD * 2) + ch * 16,
                       Abase + (size_t)row * DDIM + kofs + ch * 8);
            cp_async16(sbase + G_B_OFF + buf * G_TILE_BYTES + row * (GPAD * 2) + ch * 16,
                       Bbase + (size_t)row * DDIM + kofs + ch * 8);
        }
    };

    load_stage(0, 0);
    cp_commit();

    int buf = 0;
#pragma unroll
    for (int kt = 0; kt < DDIM / GBK; kt++) {
        if (kt + 1 < DDIM / GBK) {
            load_stage(buf ^ 1, kt + 1);
            cp_commit();
            cp_wait<1>();
        } else {
            cp_wait<0>();
        }
        __syncthreads();

        const uint32_t aBuf = sbase + buf * G_TILE_BYTES;
        const uint32_t bBuf = sbase + G_B_OFF + buf * G_TILE_BYTES;

#pragma unroll
        for (int ks = 0; ks < GBK / 16; ks++) {
            uint32_t afr[2][4];
#pragma unroll
            for (int mi = 0; mi < 2; mi++) {
                int r = wm + mi * 16 + (lane & 15);
                int c = ks * 16 + (lane >> 4) * 8;
                ldm_x4(afr[mi][0], afr[mi][1], afr[mi][2], afr[mi][3],
                       aBuf + r * (GPAD * 2) + c * 2);
            }
            uint32_t bfr[4][4];
#pragma unroll
            for (int bi = 0; bi < 4; bi++) {
                int r = wn + bi * 16 + (lane & 7) + ((lane >> 4) << 3);
                int c = ks * 16 + ((lane >> 3) & 1) * 8;
                ldm_x4(bfr[bi][0], bfr[bi][1], bfr[bi][2], bfr[bi][3],
                       bBuf + r * (GPAD * 2) + c * 2);
            }
#pragma unroll
            for (int mi = 0; mi < 2; mi++)
#pragma unroll
                for (int bi = 0; bi < 4; bi++) {
                    mma_bf16(acc[mi][bi * 2 + 0], afr[mi], &bfr[bi][0]);
                    mma_bf16(acc[mi][bi * 2 + 1], afr[mi], &bfr[bi][2]);
                }
        }
        __syncthreads();
        buf ^= 1;
    }

#pragma unroll
    for (int mi = 0; mi < 2; mi++)
#pragma unroll
        for (int nj = 0; nj < 8; nj++) {
            int col = bn + wn + nj * 8 + (lane & 3) * 2;
            float b0 = __ldg(&bias[col]);
            float b1 = __ldg(&bias[col + 1]);
            int r0 = bm + wm + mi * 16 + (lane >> 2);
            float v00 = acc[mi][nj][0] + b0, v01 = acc[mi][nj][1] + b1;
            float v10 = acc[mi][nj][2] + b0, v11 = acc[mi][nj][3] + b1;
            if (ACT) {
                v00 = v00 > 0.f ? v00 : expm1f(v00);
                v01 = v01 > 0.f ? v01 : expm1f(v01);
                v10 = v10 > 0.f ? v10 : expm1f(v10);
                v11 = v11 > 0.f ? v11 : expm1f(v11);
                *reinterpret_cast<__nv_bfloat162*>(Ch + (size_t)r0 * DDIM + col)
                    = __floats2bfloat162_rn(v00, v01);
                *reinterpret_cast<__nv_bfloat162*>(Ch + (size_t)(r0 + 8) * DDIM + col)
                    = __floats2bfloat162_rn(v10, v11);
            } else {
                *reinterpret_cast<float2*>(Cf + (size_t)r0 * DDIM + col)
                    = make_float2(v00, v01);
                *reinterpret_cast<float2*>(Cf + (size_t)(r0 + 8) * DDIM + col)
                    = make_float2(v10, v11);
            }
        }
}

// ---------------- normalize + fp8 concat + diag + zero Rall ------------------
// warp = one token n: normalize Z1[n], Z2[n] (f32 regs), write fp8 into concat
// layout, compute D12[n], zero Rall entries for this token.
__global__ void normdiag_kernel() {
    int n    = blockIdx.x * 8 + (threadIdx.x >> 5);
    int lane = threadIdx.x & 31;
    int b = n >> 12, r = n & 4095;

    const float4* p1 = reinterpret_cast<const float4*>(g_Z1 + (size_t)n * DDIM);
    const float4* p2 = reinterpret_cast<const float4*>(g_Z2 + (size_t)n * DDIM);
    float4 a0 = p1[lane], a1 = p1[lane + 32];
    float4 b0 = p2[lane], b1 = p2[lane + 32];

    float s1 = a0.x*a0.x + a0.y*a0.y + a0.z*a0.z + a0.w*a0.w
             + a1.x*a1.x + a1.y*a1.y + a1.z*a1.z + a1.w*a1.w;
    float s2 = b0.x*b0.x + b0.y*b0.y + b0.z*b0.z + b0.w*b0.w
             + b1.x*b1.x + b1.y*b1.y + b1.z*b1.z + b1.w*b1.w;
#pragma unroll
    for (int off = 16; off >= 1; off >>= 1) {
        s1 += __shfl_xor_sync(0xffffffffu, s1, off);
        s2 += __shfl_xor_sync(0xffffffffu, s2, off);
    }
    float i1 = 1.f / fmaxf(sqrtf(s1), 1e-12f);
    float i2 = 1.f / fmaxf(sqrtf(s2), 1e-12f);
    a0.x *= i1; a0.y *= i1; a0.z *= i1; a0.w *= i1;
    a1.x *= i1; a1.y *= i1; a1.z *= i1; a1.w *= i1;
    b0.x *= i2; b0.y *= i2; b0.z *= i2; b0.w *= i2;
    b1.x *= i2; b1.y *= i2; b1.z *= i2; b1.w *= i2;

    // diag dot in fp32
    float d = a0.x*b0.x + a0.y*b0.y + a0.z*b0.z + a0.w*b0.w
            + a1.x*b1.x + a1.y*b1.y + a1.z*b1.z + a1.w*b1.w;
#pragma unroll
    for (int off = 16; off >= 1; off >>= 1) d += __shfl_xor_sync(0xffffffffu, d, off);

    // write fp8 into concat layout
    uint32_t* q1 = reinterpret_cast<uint32_t*>(g_Zq + ((size_t)b * L2SEQ + r) * DDIM);
    uint32_t* q2 = reinterpret_cast<uint32_t*>(g_Zq + ((size_t)b * L2SEQ + LSEQ + r) * DDIM);
    q1[lane]      = (uint32_t)f2_e4m3x2(a0.x, a0.y) | ((uint32_t)f2_e4m3x2(a0.z, a0.w) << 16);
    q1[lane + 32] = (uint32_t)f2_e4m3x2(a1.x, a1.y) | ((uint32_t)f2_e4m3x2(a1.z, a1.w) << 16);
    q2[lane]      = (uint32_t)f2_e4m3x2(b0.x, b0.y) | ((uint32_t)f2_e4m3x2(b0.z, b0.w) << 16);
    q2[lane + 32] = (uint32_t)f2_e4m3x2(b1.x, b1.y) | ((uint32_t)f2_e4m3x2(b1.z, b1.w) << 16);

    if (lane == 0) {
        g_D12[n] = __expf(d * INV_TAU);
        g_Rall[b * L2SEQ + r] = 0.f;
        g_Rall[b * L2SEQ + LSEQ + r] = 0.f;
    }
}

// ---------------- FP8 symmetric Gram on concat Z -----------------------------
// One triangular tile (i<=j) of G_b = Zq_b . Zq_b^T. Rowsums of exp(G/tau)
// accumulate into g_Rall; off-diagonal tiles also add column sums (mirror).
__global__ __launch_bounds__(256, 2)
void gram_fp8() {
    // decode triangular tile index
    int t = blockIdx.x;
    int i = (int)((2 * NTILE + 1 - sqrtf((float)((2 * NTILE + 1) * (2 * NTILE + 1) - 8 * t))) * 0.5f);
    while ((i + 1) * NTILE - ((i + 1) * i) / 2 <= t) i++;
    while (i * NTILE - (i * (i - 1)) / 2 > t) i--;
    int j = i + (t - (i * NTILE - (i * (i - 1)) / 2));
    const bool do_col = (j != i);
    const int b = blockIdx.y;

    extern __shared__ __align__(128) char smem[];
    const uint32_t sbase = smem_u32(smem);
    const uint32_t sA = sbase + Q_A_OFF;
    const uint32_t sB = sbase + Q_B_OFF;

    const int tid  = threadIdx.x;
    const int wid  = tid >> 5;
    const int lane = tid & 31;

    const uint8_t* Abase = g_Zq + ((size_t)b * L2SEQ + i * 128) * DDIM;
    const uint8_t* Bbase = g_Zq + ((size_t)b * L2SEQ + j * 128) * DDIM;

    const int wm = (wid & 3) * 32;
    const int wn = (wid >> 2) * 64;

    // ---- 2-stage load: stage s covers K bytes [s*128, s*128+128)
#pragma unroll
    for (int s = 0; s < 2; s++) {
#pragma unroll
        for (int it = 0; it < 4; it++) {
            int idx = tid + it * 256;          // 0..1023
            int row = idx >> 3;                // 0..127
            int ch  = idx & 7;                 // 16B chunk in the 128B row
            uint32_t sw = (uint32_t)((ch ^ (row & 7)) * 16);
            cp_async16(sA + s * QSTAGE_BYTES + row * 128 + sw,
                       Abase + (size_t)row * DDIM + s * 128 + ch * 16);
            cp_async16(sB + s * QSTAGE_BYTES + row * 128 + sw,
                       Bbase + (size_t)row * DDIM + s * 128 + ch * 16);
        }
        cp_commit();
    }

    float acc[2][8][4];
#pragma unroll
    for (int mi = 0; mi < 2; mi++)
#pragma unroll
        for (int nj = 0; nj < 8; nj++)
#pragma unroll
            for (int c = 0; c < 4; c++) acc[mi][nj][c] = 0.f;

#pragma unroll
    for (int s = 0; s < 2; s++) {
        if (s == 0) cp_wait<1>(); else cp_wait<0>();
        __syncthreads();
        const uint32_t aS = sA + s * QSTAGE_BYTES;
        const uint32_t bS = sB + s * QSTAGE_BYTES;
#pragma unroll
        for (int ks = 0; ks < 4; ks++) {       // K=32 bytes each
            uint32_t afr[2][4];
#pragma unroll
            for (int mi = 0; mi < 2; mi++) {
                int r = wm + mi * 16 + (lane & 15);
                int c16 = ks * 2 + (lane >> 4);
                ldm_x4(afr[mi][0], afr[mi][1], afr[mi][2], afr[mi][3],
                       aS + r * 128 + ((c16 ^ (r & 7)) * 16));
            }
            uint32_t bfr[4][4];
#pragma unroll
            for (int bi = 0; bi < 4; bi++) {
                int r = wn + bi * 16 + (lane & 7) + ((lane >> 4) << 3);
                int c16 = ks * 2 + ((lane >> 3) & 1);
                ldm_x4(bfr[bi][0], bfr[bi][1], bfr[bi][2], bfr[bi][3],
                       bS + r * 128 + ((c16 ^ (r & 7)) * 16));
            }
#pragma unroll
            for (int mi = 0; mi < 2; mi++)
#pragma unroll
                for (int bi = 0; bi < 4; bi++) {
                    mma_e4m3(acc[mi][bi * 2 + 0], afr[mi], &bfr[bi][0]);
                    mma_e4m3(acc[mi][bi * 2 + 1], afr[mi], &bfr[bi][2]);
                }
        }
    }

    // ---- epilogue: exp + row sums (+ col sums for off-diag)
    float* Rb = g_Rall + b * L2SEQ;
    const int bm = i * 128, bn = j * 128;

    float rs[2][2] = {{0.f, 0.f}, {0.f, 0.f}};
    float cs[8][2];
#pragma unroll
    for (int nj = 0; nj < 8; nj++) { cs[nj][0] = 0.f; cs[nj][1] = 0.f; }

#pragma unroll
    for (int mi = 0; mi < 2; mi++)
#pragma unroll
        for (int nj = 0; nj < 8; nj++) {
            float e0 = __expf(acc[mi][nj][0] * INV_TAU);
            float e1 = __expf(acc[mi][nj][1] * INV_TAU);
            float e2 = __expf(acc[mi][nj][2] * INV_TAU);
            float e3 = __expf(acc[mi][nj][3] * INV_TAU);
            rs[mi][0] += e0 + e1;
            rs[mi][1] += e2 + e3;
            cs[nj][0] += e0 + e2;
            cs[nj][1] += e1 + e3;
        }

#pragma unroll
    for (int off = 1; off <= 2; off <<= 1)
#pragma unroll
        for (int mi = 0; mi < 2; mi++) {
            rs[mi][0] += __shfl_xor_sync(0xffffffffu, rs[mi][0], off);
            rs[mi][1] += __shfl_xor_sync(0xffffffffu, rs[mi][1], off);
        }
    if ((lane & 3) == 0) {
#pragma unroll
        for (int mi = 0; mi < 2; mi++) {
            int row = bm + wm + mi * 16 + (lane >> 2);
            atomicAdd(&Rb[row], rs[mi][0]);
            atomicAdd(&Rb[row + 8], rs[mi][1]);
        }
    }

    if (do_col) {
#pragma unroll
        for (int off = 4; off <= 16; off <<= 1)
#pragma unroll
            for (int nj = 0; nj < 8; nj++) {
                cs[nj][0] += __shfl_xor_sync(0xffffffffu, cs[nj][0], off);
                cs[nj][1] += __shfl_xor_sync(0xffffffffu, cs[nj][1], off);
            }
        if (lane < 4) {
#pragma unroll
            for (int nj = 0; nj < 8; nj++) {
                int col = bn + wn + nj * 8 + lane * 2;
                atomicAdd(&Rb[col], cs[nj][0]);
                atomicAdd(&Rb[col + 1], cs[nj][1]);
            }
        }
    }
}

// ---------------- final scalar reduction -------------------------------------
__global__ void final_kernel(float* __restrict__ out) {
    __shared__ double sred[256];
    const float E2 = 7.3890560989306495f;   // exp(||z||^2 / tau) = exp(2)
    double acc = 0.0;
    for (int n = threadIdx.x; n < NTOK; n += 256) {
        int b = n >> 12, r = n & 4095;
        float d1 = g_Rall[b * L2SEQ + r] - E2;
        float d2 = g_Rall[b * L2SEQ + LSEQ + r] - E2;
        acc += (double)(logf(d1) + logf(d2) - 2.f * logf(g_D12[n]));
    }
    sred[threadIdx.x] = acc;
    __syncthreads();
    for (int s = 128; s > 0; s >>= 1) {
        if (threadIdx.x < s) sred[threadIdx.x] += sred[threadIdx.x + s];
        __syncthreads();
    }
    if (threadIdx.x == 0) out[0] = (float)(sred[0] / (2.0 * BATCH));
}

// ---------------- launch -------------------------------------------------------
extern "C" void kernel_launch(void* const* d_in, const int* in_sizes, int n_in,
                              void* d_out, int out_size) {
    (void)in_sizes; (void)n_in; (void)out_size;
    const float* X1 = (const float*)d_in[0];
    const float* X2 = (const float*)d_in[1];
    const float* W1 = (const float*)d_in[2];
    const float* b1 = (const float*)d_in[3];
    const float* W2 = (const float*)d_in[4];
    const float* b2 = (const float*)d_in[5];
    float* out = (float*)d_out;

    cudaFuncSetAttribute(proj_mma<0>, cudaFuncAttributeMaxDynamicSharedMemorySize, G_SMEM_TOTAL);
    cudaFuncSetAttribute(proj_mma<1>, cudaFuncAttributeMaxDynamicSharedMemorySize, G_SMEM_TOTAL);
    cudaFuncSetAttribute(gram_fp8, cudaFuncAttributeMaxDynamicSharedMemorySize, Q_SMEM_TOTAL);

    const int NX4 = NTOK * DDIM / 4;
    const int NW4 = DDIM * DDIM / 4;
    cvtX_kernel<<<2 * NX4 / 256, 256>>>(X1, X2, NX4);                 // launch 0
    cvtW_kernel<<<(2 * NW4 + 255) / 256, 256>>>(W1, W2, NW4);         // launch 1

    dim3 gproj(DDIM / GBN, NTOK / GBM, 2);
    proj_mma<1><<<gproj, 256, G_SMEM_TOTAL>>>(b1);                    // launch 2
    proj_mma<0><<<gproj, 256, G_SMEM_TOTAL>>>(b2);                    // launch 3

    normdiag_kernel<<<NTOK / 8, 256>>>();                             // launch 4

    gram_fp8<<<dim3(NTRI, BATCH), 256, Q_SMEM_TOTAL>>>();             // launch 5

    final_kernel<<<1, 256>>>(out);                                    // launch 6
}